// round 15
// baseline (speedup 1.0000x reference)
#include <cuda_runtime.h>

// Net_90434831385322: z = LIM_A + span*sigmoid( relu(((x-LIM_A)/span) @ W1 + b1) @ W2 + b2 )
//
// R15 (delta vs R14 best): lane packing switched from j-pairs back to ROW
// pairs, now that weights live in the const bank (UR operands). Row-pair
// packing halves per-row GPR state (xp 8->4, y 8->4 regs/row), enabling 8
// rows/thread without spills; duplicated weights only cost extra LDCU
// (uniform port, not the bottleneck). Epilogue loses the even/odd merge.

typedef unsigned long long u64;

__device__ __forceinline__ u64 ffma2(u64 a, u64 b, u64 c) {
    u64 d;
    asm("fma.rn.f32x2 %0, %1, %2, %3;" : "=l"(d) : "l"(a), "l"(b), "l"(c));
    return d;
}
__device__ __forceinline__ u64 pack2(float lo, float hi) {
    u64 d;
    asm("mov.b64 %0, {%1, %2};" : "=l"(d) : "f"(lo), "f"(hi));
    return d;
}
__device__ __forceinline__ void unpack2(u64 v, float& lo, float& hi) {
    asm("mov.b64 {%0, %1}, %2;" : "=f"(lo), "=f"(hi) : "l"(v));
}
__device__ __forceinline__ u64 relu2(u64 h) {
    float a, b;
    unpack2(h, a, b);
    a = fmaxf(a, 0.0f);
    b = fmaxf(b, 0.0f);
    return pack2(a, b);
}
__device__ __forceinline__ float tanh_approx(float v) {
    float r;
    asm("tanh.approx.f32 %0, %1;" : "=f"(r) : "f"(v));
    return r;
}

#define HID 64
#define NPR 4              // row-pairs per thread (8 rows)
#define ROWS_PER_WARP 256  // 32 lanes * 8 rows

// Per hidden unit j, weights duplicated into both f32x2 lanes:
//  A[j] = (dup w1f0, dup w1f1)   B[j] = (dup w1f2, dup w1f3)
//  C[j] = (dup w2_0, dup w2_1)   D[j] = (dup w2_2, dup w2_3)
//  E[j] = dup b1f
struct Fold {
    ulonglong2 A[HID];
    ulonglong2 B[HID];
    ulonglong2 C[HID];
    ulonglong2 D[HID];
    u64        E[HID];
    float      bb[4];
};

__device__    Fold gFold;   // staging (written by setup kernel)
__constant__  Fold cFold;   // read by main kernel via const path (LDCU->UR)

__global__ void fold_kernel(const float* __restrict__ W1,   // [4][64]
                            const float* __restrict__ b1,   // [64]
                            const float* __restrict__ W2,   // [64][4]
                            const float* __restrict__ b2)   // [4]
{
    const int j = threadIdx.x;
    if (j < HID) {
        const float lim_a[4]    = {0.001f, 0.02f, 0.05f, 0.001f};
        const float inv_span[4] = {1.0f/0.003f, 1.0f/0.03f, 1.0f/0.15f, 1.0f/0.003f};
        float w[4];
        float bf = b1[j];
        #pragma unroll
        for (int i = 0; i < 4; i++) {
            w[i] = W1[i * HID + j] * inv_span[i];
            bf -= lim_a[i] * w[i];
        }
        gFold.A[j] = make_ulonglong2(pack2(w[0], w[0]), pack2(w[1], w[1]));
        gFold.B[j] = make_ulonglong2(pack2(w[2], w[2]), pack2(w[3], w[3]));
        gFold.C[j] = make_ulonglong2(pack2(W2[j*4+0], W2[j*4+0]),
                                     pack2(W2[j*4+1], W2[j*4+1]));
        gFold.D[j] = make_ulonglong2(pack2(W2[j*4+2], W2[j*4+2]),
                                     pack2(W2[j*4+3], W2[j*4+3]));
        gFold.E[j] = pack2(bf, bf);
        if (j < 4) gFold.bb[j] = b2[j];
    }
}

__global__ void __launch_bounds__(128, 4)
mlp_kernel(const float4* __restrict__ x,
           float4* __restrict__ out,
           int rows)
{
    const int t = threadIdx.x;
    const int lane = t & 31;
    const int warp = t >> 5;
    const int warpsPerBlock = blockDim.x >> 5;
    const int base = (blockIdx.x * warpsPerBlock + warp) * ROWS_PER_WARP + lane;

    const bool full = (base + 32 * (2 * NPR - 1)) < rows;

    // ---- load 8 rows, pack row-pairs as u64 lanes ----
    u64 xp[NPR][4];
    #pragma unroll
    for (int pr = 0; pr < NPR; pr++) {
        int r0 = base + 32 * (2 * pr);
        int r1 = r0 + 32;
        if (!full) {
            r0 = r0 < rows ? r0 : (rows - 1);
            r1 = r1 < rows ? r1 : (rows - 1);
        }
        const float4 a = x[r0];
        const float4 b = x[r1];
        xp[pr][0] = pack2(a.x, b.x);
        xp[pr][1] = pack2(a.y, b.y);
        xp[pr][2] = pack2(a.z, b.z);
        xp[pr][3] = pack2(a.w, b.w);
    }

    // ---- accumulators: y[pr][k] = (y_k row0, y_k row1), b2 pre-loaded ----
    u64 y[NPR][4];
    #pragma unroll
    for (int pr = 0; pr < NPR; pr++) {
        #pragma unroll
        for (int k = 0; k < 4; k++) {
            y[pr][k] = pack2(cFold.bb[k], cFold.bb[k]);
        }
    }

    // ---- fused layer1 + relu + layer2 over 64 hidden units ----
    #pragma unroll 8
    for (int j = 0; j < HID; j++) {
        const ulonglong2 wA = cFold.A[j];
        const ulonglong2 wB = cFold.B[j];
        const ulonglong2 wC = cFold.C[j];
        const ulonglong2 wD = cFold.D[j];
        const u64 b1d = cFold.E[j];

        #pragma unroll
        for (int pr = 0; pr < NPR; pr++) {
            u64 h = ffma2(xp[pr][0], wA.x, b1d);
            h = ffma2(xp[pr][1], wA.y, h);
            h = ffma2(xp[pr][2], wB.x, h);
            h = ffma2(xp[pr][3], wB.y, h);
            h = relu2(h);   // (h_j row0, h_j row1)
            y[pr][0] = ffma2(h, wC.x, y[pr][0]);
            y[pr][1] = ffma2(h, wC.y, y[pr][1]);
            y[pr][2] = ffma2(h, wD.x, y[pr][2]);
            y[pr][3] = ffma2(h, wD.y, y[pr][3]);
        }
    }

    // ---- tanh epilogue + coalesced stores (no lane merge needed) ----
    //  z_k = (lim_a_k + span_k/2) + (span_k/2) * tanh(y_k/2)
    const float c0_k[4] = {0.0025f, 0.035f, 0.125f, 0.0025f};
    const float c1_k[4] = {0.0015f, 0.015f, 0.075f, 0.0015f};

    #pragma unroll
    for (int pr = 0; pr < NPR; pr++) {
        float4 o0, o1;
        float* p0 = &o0.x;
        float* p1 = &o1.x;
        #pragma unroll
        for (int k = 0; k < 4; k++) {
            float v0, v1;
            unpack2(y[pr][k], v0, v1);
            const float t0 = tanh_approx(0.5f * v0);
            const float t1 = tanh_approx(0.5f * v1);
            p0[k] = fmaf(c1_k[k], t0, c0_k[k]);
            p1[k] = fmaf(c1_k[k], t1, c0_k[k]);
        }
        const int r0 = base + 32 * (2 * pr);
        const int r1 = r0 + 32;
        if (full) {
            out[r0] = o0;
            out[r1] = o1;
        } else {
            if (r0 < rows) out[r0] = o0;
            if (r1 < rows) out[r1] = o1;
        }
    }
}

extern "C" void kernel_launch(void* const* d_in, const int* in_sizes, int n_in,
                              void* d_out, int out_size) {
    const float* x  = (const float*)d_in[0];
    const float* W1 = (const float*)d_in[1];
    const float* b1 = (const float*)d_in[2];
    const float* W2 = (const float*)d_in[3];
    const float* b2 = (const float*)d_in[4];
    const int rows = in_sizes[0] / 4;

    // 1) fold weights into staging global
    fold_kernel<<<1, 64>>>(W1, b1, W2, b2);

    // 2) D2D copy into __constant__ (graph-capturable memcpy node)
    void* gptr = nullptr;
    cudaGetSymbolAddress(&gptr, gFold);
    cudaMemcpyToSymbolAsync(cFold, gptr, sizeof(Fold), 0,
                            cudaMemcpyDeviceToDevice);

    // 3) main kernel: flat grid, one 256-row tile per warp, 128-thread CTAs
    const int threads = 128;
    const int rowsPerBlock = (threads / 32) * ROWS_PER_WARP;  // 1024
    const int blocks = (rows + rowsPerBlock - 1) / rowsPerBlock;  // 4096
    mlp_kernel<<<blocks, threads>>>((const float4*)x, (float4*)d_out, rows);
}

// round 16
// speedup vs baseline: 1.0288x; 1.0288x over previous
#include <cuda_runtime.h>

// Net_90434831385322: z = LIM_A + span*sigmoid( relu(((x-LIM_A)/span) @ W1 + b1) @ W2 + b2 )
//
// R16 = R14 (best: const-bank weights LDCU->UR, j-pair f32x2 lanes, NR=6 rows
// per thread, tanh epilogue, 128-thread CTAs) with the jp loop FULLY UNROLLED.
// Rationale: unroll-8 groups force LDCU scheduling horizons of ~3 iterations
// (64-UR file vs 18 URs/iter); a flat body lets ptxas hoist const loads across
// the whole 1536-ffma2 stream and drops loop-end overhead.
// R15's row-pair/const combo regressed (2x const traffic) - reverted.

typedef unsigned long long u64;

__device__ __forceinline__ u64 ffma2(u64 a, u64 b, u64 c) {
    u64 d;
    asm("fma.rn.f32x2 %0, %1, %2, %3;" : "=l"(d) : "l"(a), "l"(b), "l"(c));
    return d;
}
__device__ __forceinline__ u64 pack2(float lo, float hi) {
    u64 d;
    asm("mov.b64 %0, {%1, %2};" : "=l"(d) : "f"(lo), "f"(hi));
    return d;
}
__device__ __forceinline__ void unpack2(u64 v, float& lo, float& hi) {
    asm("mov.b64 {%0, %1}, %2;" : "=f"(lo), "=f"(hi) : "l"(v));
}
__device__ __forceinline__ u64 relu2(u64 h) {
    float a, b;
    unpack2(h, a, b);
    a = fmaxf(a, 0.0f);
    b = fmaxf(b, 0.0f);
    return pack2(a, b);
}
__device__ __forceinline__ float tanh_approx(float v) {
    float r;
    asm("tanh.approx.f32 %0, %1;" : "=f"(r) : "f"(v));
    return r;
}

#define HID 64
#define NJP 32             // hidden-unit pairs
#define NR 6               // rows per thread
#define ROWS_PER_WARP 192  // 32 lanes * 6 rows

struct Fold {
    ulonglong2 A[NJP];
    ulonglong2 B[NJP];
    ulonglong2 C[NJP];
    ulonglong2 D[NJP];
    u64        E[NJP];
    float      bb[4];
};

__device__    Fold gFold;   // staging (written by setup kernel)
__constant__  Fold cFold;   // read by main kernel via const path (LDCU->UR)

__global__ void fold_kernel(const float* __restrict__ W1,   // [4][64]
                            const float* __restrict__ b1,   // [64]
                            const float* __restrict__ W2,   // [64][4]
                            const float* __restrict__ b2)   // [4]
{
    const int jp = threadIdx.x;
    if (jp < NJP) {
        const float lim_a[4]    = {0.001f, 0.02f, 0.05f, 0.001f};
        const float inv_span[4] = {1.0f/0.003f, 1.0f/0.03f, 1.0f/0.15f, 1.0f/0.003f};
        const int j0 = 2 * jp, j1 = 2 * jp + 1;
        float w0[4], w1[4];
        float bf0 = b1[j0], bf1 = b1[j1];
        #pragma unroll
        for (int i = 0; i < 4; i++) {
            w0[i] = W1[i * HID + j0] * inv_span[i];
            w1[i] = W1[i * HID + j1] * inv_span[i];
            bf0 -= lim_a[i] * w0[i];
            bf1 -= lim_a[i] * w1[i];
        }
        gFold.A[jp] = make_ulonglong2(pack2(w0[0], w1[0]), pack2(w0[1], w1[1]));
        gFold.B[jp] = make_ulonglong2(pack2(w0[2], w1[2]), pack2(w0[3], w1[3]));
        gFold.C[jp] = make_ulonglong2(pack2(W2[j0*4+0], W2[j1*4+0]),
                                      pack2(W2[j0*4+1], W2[j1*4+1]));
        gFold.D[jp] = make_ulonglong2(pack2(W2[j0*4+2], W2[j1*4+2]),
                                      pack2(W2[j0*4+3], W2[j1*4+3]));
        gFold.E[jp] = pack2(bf0, bf1);
        if (jp < 4) gFold.bb[jp] = b2[jp];
    }
}

__global__ void __launch_bounds__(128, 4)
mlp_kernel(const float4* __restrict__ x,
           float4* __restrict__ out,
           int rows)
{
    const int t = threadIdx.x;
    const int lane = t & 31;
    const int warp = t >> 5;
    const int warpsPerBlock = blockDim.x >> 5;
    const int base = (blockIdx.x * warpsPerBlock + warp) * ROWS_PER_WARP + lane;

    const bool full = (base + 32 * (NR - 1)) < rows;

    // ---- load NR rows, duplicate each x_i into both lanes ----
    u64 xd[NR][4];
    #pragma unroll
    for (int rr = 0; rr < NR; rr++) {
        int r = base + 32 * rr;
        if (!full) r = r < rows ? r : (rows - 1);
        const float4 a = x[r];
        xd[rr][0] = pack2(a.x, a.x);
        xd[rr][1] = pack2(a.y, a.y);
        xd[rr][2] = pack2(a.z, a.z);
        xd[rr][3] = pack2(a.w, a.w);
    }

    // ---- accumulators: lanes = (partial even j, partial odd j);
    //      b2 bias pre-loaded into the even lane ----
    u64 y[NR][4];
    #pragma unroll
    for (int rr = 0; rr < NR; rr++) {
        #pragma unroll
        for (int k = 0; k < 4; k++) {
            y[rr][k] = pack2(cFold.bb[k], 0.0f);
        }
    }

    // ---- fused layer1 + relu + layer2, FULLY unrolled over 32 j-pairs ----
    #pragma unroll
    for (int jp = 0; jp < NJP; jp++) {
        const ulonglong2 wA = cFold.A[jp];
        const ulonglong2 wB = cFold.B[jp];
        const ulonglong2 wC = cFold.C[jp];
        const ulonglong2 wD = cFold.D[jp];
        const u64 b1d = cFold.E[jp];

        #pragma unroll
        for (int rr = 0; rr < NR; rr++) {
            u64 h = ffma2(xd[rr][0], wA.x, b1d);
            h = ffma2(xd[rr][1], wA.y, h);
            h = ffma2(xd[rr][2], wB.x, h);
            h = ffma2(xd[rr][3], wB.y, h);
            h = relu2(h);   // (h_j, h_j+1) for this row
            y[rr][0] = ffma2(h, wC.x, y[rr][0]);
            y[rr][1] = ffma2(h, wC.y, y[rr][1]);
            y[rr][2] = ffma2(h, wD.x, y[rr][2]);
            y[rr][3] = ffma2(h, wD.y, y[rr][3]);
        }
    }

    // ---- tanh epilogue + coalesced stores ----
    //  z_k = (lim_a_k + span_k/2) + (span_k/2) * tanh(y_k/2)
    const float c0_k[4] = {0.0025f, 0.035f, 0.125f, 0.0025f};
    const float c1_k[4] = {0.0015f, 0.015f, 0.075f, 0.0015f};

    #pragma unroll
    for (int rr = 0; rr < NR; rr++) {
        float4 o;
        float* p = &o.x;
        #pragma unroll
        for (int k = 0; k < 4; k++) {
            float ye, yo;
            unpack2(y[rr][k], ye, yo);
            const float yk = ye + yo;          // bias already in ye
            const float th = tanh_approx(0.5f * yk);
            p[k] = fmaf(c1_k[k], th, c0_k[k]);
        }
        const int r = base + 32 * rr;
        if (full) {
            out[r] = o;
        } else {
            if (r < rows) out[r] = o;
        }
    }
}

extern "C" void kernel_launch(void* const* d_in, const int* in_sizes, int n_in,
                              void* d_out, int out_size) {
    const float* x  = (const float*)d_in[0];
    const float* W1 = (const float*)d_in[1];
    const float* b1 = (const float*)d_in[2];
    const float* W2 = (const float*)d_in[3];
    const float* b2 = (const float*)d_in[4];
    const int rows = in_sizes[0] / 4;

    // 1) fold weights into staging global
    fold_kernel<<<1, 32>>>(W1, b1, W2, b2);

    // 2) D2D copy into __constant__ (graph-capturable memcpy node)
    void* gptr = nullptr;
    cudaGetSymbolAddress(&gptr, gFold);
    cudaMemcpyToSymbolAsync(cFold, gptr, sizeof(Fold), 0,
                            cudaMemcpyDeviceToDevice);

    // 3) main kernel: flat grid, one 192-row tile per warp, 128-thread CTAs
    const int threads = 128;
    const int rowsPerBlock = (threads / 32) * ROWS_PER_WARP;  // 768
    const int blocks = (rows + rowsPerBlock - 1) / rowsPerBlock;  // 5462
    mlp_kernel<<<blocks, threads>>>((const float4*)x, (float4*)d_out, rows);
}